// round 14
// baseline (speedup 1.0000x reference)
#include <cuda_runtime.h>
#include <math_constants.h>
#include <cstdint>

#define BB 4
#define TT 2048
#define CC 1024
#define HH 128
#define BT (BB * TT)

// packed bf16-pair planes (one u32 = 2 adjacent bf16)
__device__ uint32_t g_wh[3 * CC * HH / 2], g_wl[3 * CC * HH / 2];
__device__ uint32_t g_qh[BT * HH / 2], g_ql[BT * HH / 2];
__device__ uint32_t g_kh[BT * HH / 2], g_kl[BT * HH / 2];
__device__ uint32_t g_vh[BT * HH / 2], g_vl[BT * HH / 2];
// attention partials: [B][16 qblocks][8 chunks]  (fixed-max: only l + O)
__device__ float g_po[BB * 16 * 8 * 128 * HH];
__device__ float g_pl[BB * 16 * 8 * 128];

// ---------------------------------------------------------------------------
// helpers
// ---------------------------------------------------------------------------
__device__ __forceinline__ uint32_t bf2(float lo, float hi) {
    uint32_t r;
    asm("cvt.rn.bf16x2.f32 %0, %1, %2;" : "=r"(r) : "f"(hi), "f"(lo));
    return r;
}
__device__ __forceinline__ void split2(float a, float b, uint32_t& h, uint32_t& l) {
    h = bf2(a, b);
    float ah = __uint_as_float(h << 16);
    float bh = __uint_as_float(h & 0xffff0000u);
    l = bf2(a - ah, b - bh);
}
__device__ __forceinline__ float ex2(float x) {
    float r;
    asm("ex2.approx.f32 %0, %1;" : "=f"(r) : "f"(x));
    return r;
}
__device__ __forceinline__ void mma16816(float c[4], const uint32_t a[4],
                                         uint32_t b0, uint32_t b1) {
    asm volatile(
        "mma.sync.aligned.m16n8k16.row.col.f32.bf16.bf16.f32 "
        "{%0,%1,%2,%3}, {%4,%5,%6,%7}, {%8,%9}, {%0,%1,%2,%3};"
        : "+f"(c[0]), "+f"(c[1]), "+f"(c[2]), "+f"(c[3])
        : "r"(a[0]), "r"(a[1]), "r"(a[2]), "r"(a[3]), "r"(b0), "r"(b1));
}
__device__ __forceinline__ void ldsm4(uint32_t* r, uint32_t addr) {
    asm volatile("ldmatrix.sync.aligned.m8n8.x4.shared.b16 {%0,%1,%2,%3}, [%4];"
                 : "=r"(r[0]), "=r"(r[1]), "=r"(r[2]), "=r"(r[3]) : "r"(addr));
}
__device__ __forceinline__ void ldsm4t(uint32_t* r, uint32_t addr) {
    asm volatile("ldmatrix.sync.aligned.m8n8.x4.trans.shared.b16 {%0,%1,%2,%3}, [%4];"
                 : "=r"(r[0]), "=r"(r[1]), "=r"(r[2]), "=r"(r[3]) : "r"(addr));
}
__device__ __forceinline__ void cpa16(uint32_t s, const void* g) {
    asm volatile("cp.async.cg.shared.global [%0], [%1], 16;" :: "r"(s), "l"(g));
}
__device__ __forceinline__ void cpa_commit() { asm volatile("cp.async.commit_group;"); }
__device__ __forceinline__ void cpa_wait0()  { asm volatile("cp.async.wait_group 0;"); }
__device__ __forceinline__ void cpa_wait1()  { asm volatile("cp.async.wait_group 1;"); }

// ---------------------------------------------------------------------------
// fp32 -> bf16 hi/lo planes for the three weight matrices only
// ---------------------------------------------------------------------------
#define N4W (CC * HH / 4)

__global__ void convert_kernel(const float* __restrict__ wq,
                               const float* __restrict__ wk,
                               const float* __restrict__ wv)
{
    int i = blockIdx.x * blockDim.x + threadIdx.x;
    if (i >= 3 * N4W) return;
    int w = i / N4W;
    int idx = i - w * N4W;
    const float* src = (w == 0) ? wq : (w == 1) ? wk : wv;
    uint32_t* dh = g_wh + w * (CC * HH / 2);
    uint32_t* dl = g_wl + w * (CC * HH / 2);
    float4 v = ((const float4*)src)[idx];
    uint32_t h0, l0, h1, l1;
    split2(v.x, v.y, h0, l0);
    split2(v.z, v.w, h1, l1);
    ((uint2*)dh)[idx] = make_uint2(h0, h1);
    ((uint2*)dl)[idx] = make_uint2(l0, l1);
}

// ---------------------------------------------------------------------------
// FUSED Q/K/V projection GEMM: one block computes all three 64x128 outputs.
// x loaded by direct LDG with register prefetch, converted to bf16 hi/lo
// ONCE, A-fragments reused for 3 weight sets.  W cp.async double-buffered.
// Block 64(M) x 128(N) x 3 outputs, BK=32.  8 warps = 4(M) x 2(N).
// Grid = 128 blocks (single wave).
// ---------------------------------------------------------------------------
#define XPL 5120                 // one x plane (64 rows x 80B)
#define XHOF(b) ((uint32_t)(b) * XPL)
#define XLOF(b) (2 * XPL + (uint32_t)(b) * XPL)
#define WB0  20480
#define WSEG 8704                // one W plane (32 rows x 272B)
#define WBUF 52224               // 3y x 2 planes
#define WOF(b, y, hl) (WB0 + (uint32_t)(b) * WBUF + (uint32_t)(y) * 17408 + (uint32_t)(hl) * WSEG)
#define PROJ_SMEM 124928

__global__ __launch_bounds__(256) void proj_kernel(const float* __restrict__ x)
{
    extern __shared__ char ps[];
    const uint32_t sb = (uint32_t)__cvta_generic_to_shared(ps);
    const int tid = threadIdx.x, lane = tid & 31, wid = tid >> 5;
    const int wm = wid & 3, wn = wid >> 2;
    const int g = lane >> 2, tg = lane & 3;
    const int m0 = blockIdx.x * 64;

    float acc[3][8][4];
#pragma unroll
    for (int y = 0; y < 3; y++)
#pragma unroll
        for (int nt = 0; nt < 8; nt++)
#pragma unroll
            for (int i = 0; i < 4; i++) acc[y][nt][i] = 0.f;

    const uint32_t a_coff = (lane >> 4) * 16;
    const uint32_t b_coff = (uint32_t)(wn * 128 + (lane >> 4) * 16);

    // W loader: 3y x 2 planes x 512 segs = 3072 segs -> 12 per thread
    auto load_W = [&](int k0, int b) {
#pragma unroll
        for (int i = 0; i < 12; i++) {
            int j = tid + i * 256;
            int pl = j >> 9;              // 0..5
            int y = pl >> 1, hl = pl & 1;
            int r = (j >> 4) & 31, cs = j & 15;
            const uint32_t* wsrc = (hl ? g_wl : g_wh) + (size_t)y * (CC * HH / 2)
                                 + (size_t)(k0 + r) * 64 + cs * 4;
            cpa16(sb + WOF(b, y, hl) + r * 272 + cs * 16, wsrc);
        }
    };

    // x register prefetch: each thread 1 row x 8 cols
    const int xrow = tid >> 2, xcb = (tid & 3) * 8;
    const float* xp = x + (size_t)(m0 + xrow) * CC + xcb;
    float4 xr0, xr1;

    load_W(0, 0);
    cpa_commit();
    xr0 = *(const float4*)(xp);
    xr1 = *(const float4*)(xp + 4);

    for (int it = 0; it < 32; it++) {
        const int b = it & 1;
        if (it + 1 < 32) {
            load_W((it + 1) * 32, b ^ 1);
            cpa_commit();
            cpa_wait1();
        } else {
            cpa_wait0();
        }

        // convert prefetched x regs -> hi/lo planes [b]
        {
            uint32_t hh[4], ll[4];
            split2(xr0.x, xr0.y, hh[0], ll[0]);
            split2(xr0.z, xr0.w, hh[1], ll[1]);
            split2(xr1.x, xr1.y, hh[2], ll[2]);
            split2(xr1.z, xr1.w, hh[3], ll[3]);
            *(uint4*)(ps + XHOF(b) + xrow * 80 + (tid & 3) * 16) =
                make_uint4(hh[0], hh[1], hh[2], hh[3]);
            *(uint4*)(ps + XLOF(b) + xrow * 80 + (tid & 3) * 16) =
                make_uint4(ll[0], ll[1], ll[2], ll[3]);
        }
        __syncthreads();

        // prefetch x for next iter
        if (it + 1 < 32) {
            xr0 = *(const float4*)(xp + (it + 1) * 32);
            xr1 = *(const float4*)(xp + (it + 1) * 32 + 4);
        }

#pragma unroll
        for (int ks = 0; ks < 2; ks++) {
            uint32_t ah[4], al[4];
            {
                uint32_t r = wm * 16 + (lane & 15);
                ldsm4(ah, sb + XHOF(b) + r * 80 + ks * 32 + a_coff);
                ldsm4(al, sb + XLOF(b) + r * 80 + ks * 32 + a_coff);
            }
#pragma unroll
            for (int y = 0; y < 3; y++) {
#pragma unroll
                for (int np = 0; np < 4; np++) {
                    uint32_t bh[4], bl[4];
                    uint32_t r = ks * 16 + (lane & 15);
                    ldsm4t(bh, sb + WOF(b, y, 0) + r * 272 + b_coff + np * 32);
                    ldsm4t(bl, sb + WOF(b, y, 1) + r * 272 + b_coff + np * 32);
#pragma unroll
                    for (int h2 = 0; h2 < 2; h2++) {
                        float* c = acc[y][np * 2 + h2];
                        mma16816(c, ah, bh[2 * h2], bh[2 * h2 + 1]);
                        mma16816(c, ah, bl[2 * h2], bl[2 * h2 + 1]);
                        mma16816(c, al, bh[2 * h2], bh[2 * h2 + 1]);
                    }
                }
            }
        }
        __syncthreads();
    }

    // epilogue: q pre-scaled by C^-0.5 * log2(e)
    const int r1 = m0 + wm * 16 + g;
#pragma unroll
    for (int y = 0; y < 3; y++) {
        uint32_t* oh = (y == 0) ? g_qh : (y == 1) ? g_kh : g_vh;
        uint32_t* ol = (y == 0) ? g_ql : (y == 1) ? g_kl : g_vl;
        const float sc = (y == 0) ? 0.03125f * 1.44269504f : 1.0f;
#pragma unroll
        for (int nt = 0; nt < 8; nt++) {
            const int c = wn * 64 + nt * 8 + 2 * tg;
            uint32_t h, l;
            split2(acc[y][nt][0] * sc, acc[y][nt][1] * sc, h, l);
            oh[(size_t)r1 * 64 + (c >> 1)] = h;
            ol[(size_t)r1 * 64 + (c >> 1)] = l;
            split2(acc[y][nt][2] * sc, acc[y][nt][3] * sc, h, l);
            oh[(size_t)(r1 + 8) * 64 + (c >> 1)] = h;
            ol[(size_t)(r1 + 8) * 64 + (c >> 1)] = l;
        }
    }
}

// ---------------------------------------------------------------------------
// Flash attention, bf16 mma 3-term split, cp.async double-buffered K/V,
// FIXED-MAX softmax (M=16).  Block = 128 q rows x chunk of <=4 key tiles.
// (unchanged from 127.5us best)
// ---------------------------------------------------------------------------
#define SP 272
#define AKH 0
#define AKL 17408
#define AVH 34816
#define AVL 52224
#define ATT_BUF 69632
#define ATT_SMEM (2 * ATT_BUF)
#define SMAX 16.0f

__global__ __launch_bounds__(256) void attn_kernel(float* __restrict__ out)
{
    const int qb = blockIdx.x;                 // 0..15
    const int b  = blockIdx.y;                 // 0..3
    const int ch = blockIdx.z;                 // 0..7
    const int ntiles = 2 * qb + 2;
    if (ch * 4 >= ntiles) return;

    extern __shared__ char as_[];
    const uint32_t sb = (uint32_t)__cvta_generic_to_shared(as_);
    const int tid = threadIdx.x, lane = tid & 31, w = tid >> 5;
    const int g = lane >> 2, tg = lane & 3;
    const int r0 = qb * 128;

    // ---- stage Q (hi at 0, lo at AVH), async, then to registers
    {
        const uint32_t* sh = g_qh + (size_t)b * TT * 64;
        const uint32_t* sl = g_ql + (size_t)b * TT * 64;
#pragma unroll
        for (int i = 0; i < 8; i++) {
            int s = tid + i * 256;
            int row = s >> 4, cs = s & 15;
            size_t gi = (size_t)(r0 + row) * 64 + cs * 4;
            cpa16(sb + row * SP + cs * 16, sh + gi);
            cpa16(sb + AVH + row * SP + cs * 16, sl + gi);
        }
        cpa_commit();
        cpa_wait0();
    }
    __syncthreads();
    uint32_t qh[8][4], ql[8][4];
    {
        const uint32_t br = w * 16 + (lane & 15);
        const uint32_t co = (lane >> 4) * 16;
#pragma unroll
        for (int ks = 0; ks < 8; ks++) {
            ldsm4(qh[ks], sb + br * SP + ks * 32 + co);
            ldsm4(ql[ks], sb + AVH + br * SP + ks * 32 + co);
        }
    }
    __syncthreads();

    float o[16][4];
#pragma unroll
    for (int nt = 0; nt < 16; nt++)
#pragma unroll
        for (int i = 0; i < 4; i++) o[nt][i] = 0.f;
    float l0 = 0.f, l1 = 0.f;

    const uint32_t* khp = g_kh + (size_t)b * TT * 64;
    const uint32_t* klp = g_kl + (size_t)b * TT * 64;
    const uint32_t* vhp = g_vh + (size_t)b * TT * 64;
    const uint32_t* vlp = g_vl + (size_t)b * TT * 64;

    auto load_tile = [&](int j0, uint32_t bo) {
#pragma unroll
        for (int i = 0; i < 4; i++) {
            int s = tid + i * 256;
            int row = s >> 4, cs = s & 15;
            size_t gi = (size_t)(j0 + row) * 64 + cs * 4;
            uint32_t so = bo + row * SP + cs * 16;
            cpa16(sb + so + AKH, khp + gi);
            cpa16(sb + so + AKL, klp + gi);
            cpa16(sb + so + AVH, vhp + gi);
            cpa16(sb + so + AVL, vlp + gi);
        }
    };

    const int jt0 = ch * 4;
    const int n = min(jt0 + 4, ntiles) - jt0;

    load_tile(jt0 * 64, 0);
    cpa_commit();

    for (int it = 0; it < n; it++) {
        const int jt = jt0 + it;
        const int j0 = jt * 64;
        const uint32_t bo = (uint32_t)(it & 1) * ATT_BUF;
        if (it + 1 < n) {
            load_tile((jt + 1) * 64, bo ^ ATT_BUF);
            cpa_commit();
            cpa_wait1();
        } else {
            cpa_wait0();
        }
        __syncthreads();

        // ---- S = Q K^T  (q pre-scaled by 1/32*log2e)
        float s_[8][4];
#pragma unroll
        for (int nt = 0; nt < 8; nt++)
#pragma unroll
            for (int i = 0; i < 4; i++) s_[nt][i] = 0.f;
        {
            const uint32_t kr = (lane & 7);
            const uint32_t kc = (lane >> 3) * 16;
#pragma unroll
            for (int kp = 0; kp < 4; kp++) {
#pragma unroll
                for (int nt = 0; nt < 8; nt++) {
                    uint32_t kh4[4], kl4[4];
                    uint32_t ro = bo + (nt * 8 + kr) * SP + kp * 64 + kc;
                    ldsm4(kh4, sb + AKH + ro);
                    ldsm4(kl4, sb + AKL + ro);
                    mma16816(s_[nt], qh[2 * kp],     kh4[0], kh4[1]);
                    mma16816(s_[nt], qh[2 * kp],     kl4[0], kl4[1]);
                    mma16816(s_[nt], ql[2 * kp],     kh4[0], kh4[1]);
                    mma16816(s_[nt], qh[2 * kp + 1], kh4[2], kh4[3]);
                    mma16816(s_[nt], qh[2 * kp + 1], kl4[2], kl4[3]);
                    mma16816(s_[nt], ql[2 * kp + 1], kh4[2], kh4[3]);
                }
            }
        }

        // ---- causal mask
        if (jt >= 2 * qb) {
            const int rA = r0 + w * 16 + g, rB = rA + 8;
#pragma unroll
            for (int nt = 0; nt < 8; nt++) {
                const int c0 = j0 + nt * 8 + 2 * tg, c1 = c0 + 1;
                if (c0 > rA) s_[nt][0] = -CUDART_INF_F;
                if (c1 > rA) s_[nt][1] = -CUDART_INF_F;
                if (c0 > rB) s_[nt][2] = -CUDART_INF_F;
                if (c1 > rB) s_[nt][3] = -CUDART_INF_F;
            }
        }

        // ---- fixed-max softmax: p = 2^(s - 16)
#pragma unroll
        for (int nt = 0; nt < 8; nt++) {
            s_[nt][0] = ex2(s_[nt][0] - SMAX);
            s_[nt][1] = ex2(s_[nt][1] - SMAX);
            s_[nt][2] = ex2(s_[nt][2] - SMAX);
            s_[nt][3] = ex2(s_[nt][3] - SMAX);
            l0 += s_[nt][0] + s_[nt][1];
            l1 += s_[nt][2] + s_[nt][3];
        }

        // ---- O += P V (P split to bf16 in registers)
#pragma unroll
        for (int ks = 0; ks < 4; ks++) {
            uint32_t pah[4], pal[4];
            split2(s_[2 * ks][0],     s_[2 * ks][1],     pah[0], pal[0]);
            split2(s_[2 * ks][2],     s_[2 * ks][3],     pah[1], pal[1]);
            split2(s_[2 * ks + 1][0], s_[2 * ks + 1][1], pah[2], pal[2]);
            split2(s_[2 * ks + 1][2], s_[2 * ks + 1][3], pah[3], pal[3]);
            const uint32_t vr = bo + (ks * 16 + (lane & 15)) * SP + (lane >> 4) * 16;
#pragma unroll
            for (int np = 0; np < 8; np++) {
                uint32_t vh4[4], vl4[4];
                ldsm4t(vh4, sb + AVH + vr + np * 32);
                ldsm4t(vl4, sb + AVL + vr + np * 32);
                float* c0 = o[2 * np];
                float* c1 = o[2 * np + 1];
                mma16816(c0, pah, vh4[0], vh4[1]);
                mma16816(c0, pah, vl4[0], vl4[1]);
                mma16816(c0, pal, vh4[0], vh4[1]);
                mma16816(c1, pah, vh4[2], vh4[3]);
                mma16816(c1, pah, vl4[2], vl4[3]);
                mma16816(c1, pal, vh4[2], vh4[3]);
            }
        }
        __syncthreads();
    }

    // reduce row sums across the quad (once per block)
    l0 += __shfl_xor_sync(0xffffffffu, l0, 1);
    l0 += __shfl_xor_sync(0xffffffffu, l0, 2);
    l1 += __shfl_xor_sync(0xffffffffu, l1, 1);
    l1 += __shfl_xor_sync(0xffffffffu, l1, 2);

    const int rA = w * 16 + g;
    if (ntiles <= 4) {
        const float inv0 = 1.f / l0, inv1 = 1.f / l1;
        float* op = out + ((size_t)b * TT + r0) * HH;
#pragma unroll
        for (int nt = 0; nt < 16; nt++) {
            const int c = nt * 8 + 2 * tg;
            *(float2*)(op + (size_t)rA * HH + c) =
                make_float2(o[nt][0] * inv0, o[nt][1] * inv0);
            *(float2*)(op + (size_t)(rA + 8) * HH + c) =
                make_float2(o[nt][2] * inv1, o[nt][3] * inv1);
        }
    } else {
        const size_t pb = (size_t)((b * 16 + qb) * 8 + ch);
        float* po = g_po + pb * 128 * 128;
#pragma unroll
        for (int nt = 0; nt < 16; nt++) {
            const int c = nt * 8 + 2 * tg;
            *(float2*)(po + (size_t)rA * 128 + c)       = make_float2(o[nt][0], o[nt][1]);
            *(float2*)(po + (size_t)(rA + 8) * 128 + c) = make_float2(o[nt][2], o[nt][3]);
        }
        if (tg == 0) {
            g_pl[pb * 128 + rA] = l0;  g_pl[pb * 128 + rA + 8] = l1;
        }
    }
}

// ---------------------------------------------------------------------------
// Combine split-KV partials (qb >= 2): plain sums (fixed-max -> weights = 1).
// One thread per 8 output floats.
// ---------------------------------------------------------------------------
__global__ __launch_bounds__(256) void combine_kernel(float* __restrict__ out)
{
    const int qb  = 2 + (blockIdx.x >> 3);
    const int sub = blockIdx.x & 7;
    const int b   = blockIdx.y;
    const int nc  = (2 * qb + 5) >> 2;

    const int e   = sub * 256 + threadIdx.x;
    const int row = e >> 4;
    const int c8  = (e & 15) * 8;

    const size_t pb = (size_t)(b * 16 + qb) * 8;

    float l = 0.f;
#pragma unroll 4
    for (int c = 0; c < nc; c++)
        l += __ldg(&g_pl[(pb + c) * 128 + row]);
    const float inv = 1.f / l;

    float a0 = 0.f, a1 = 0.f, a2 = 0.f, a3 = 0.f;
    float b0 = 0.f, b1 = 0.f, b2 = 0.f, b3 = 0.f;
#pragma unroll 4
    for (int c = 0; c < nc; c++) {
        const float4* base = (const float4*)(g_po + ((pb + c) * 128 + row) * 128 + c8);
        const float4 p = __ldg(base);
        const float4 q = __ldg(base + 1);
        a0 += p.x; a1 += p.y; a2 += p.z; a3 += p.w;
        b0 += q.x; b1 += q.y; b2 += q.z; b3 += q.w;
    }
    float* op = out + ((size_t)b * TT + qb * 128 + row) * HH + c8;
    *(float4*)(op)     = make_float4(a0 * inv, a1 * inv, a2 * inv, a3 * inv);
    *(float4*)(op + 4) = make_float4(b0 * inv, b1 * inv, b2 * inv, b3 * inv);
}

// ---------------------------------------------------------------------------
extern "C" void kernel_launch(void* const* d_in, const int* in_sizes, int n_in,
                              void* d_out, int out_size)
{
    (void)in_sizes; (void)n_in; (void)out_size;
    const float* x  = (const float*)d_in[0];
    const float* Wq = (const float*)d_in[1];
    const float* Wk = (const float*)d_in[2];
    const float* Wv = (const float*)d_in[3];
    float* out = (float*)d_out;

    convert_kernel<<<(3 * N4W + 255) / 256, 256>>>(Wq, Wk, Wv);

    cudaFuncSetAttribute(proj_kernel,
                         cudaFuncAttributeMaxDynamicSharedMemorySize, PROJ_SMEM);
    proj_kernel<<<BT / 64, 256, PROJ_SMEM>>>(x);

    cudaFuncSetAttribute(attn_kernel,
                         cudaFuncAttributeMaxDynamicSharedMemorySize, ATT_SMEM);
    dim3 agrid(16, BB, 8);
    attn_kernel<<<agrid, 256, ATT_SMEM>>>(out);

    dim3 cgrid(14 * 8, BB);
    combine_kernel<<<cgrid, 256>>>(out);
}

// round 15
// speedup vs baseline: 1.0226x; 1.0226x over previous
#include <cuda_runtime.h>
#include <math_constants.h>
#include <cstdint>

#define BB 4
#define TT 2048
#define CC 1024
#define HH 128
#define BT (BB * TT)

// packed bf16-pair planes (one u32 = 2 adjacent bf16)
__device__ uint32_t g_wh[3 * CC * HH / 2], g_wl[3 * CC * HH / 2];
__device__ uint32_t g_qh[BT * HH / 2], g_ql[BT * HH / 2];
__device__ uint32_t g_kh[BT * HH / 2], g_kl[BT * HH / 2];
__device__ uint32_t g_vh[BT * HH / 2], g_vl[BT * HH / 2];
// attention partials: [B][16 qblocks][8 chunks]  (fixed-max: only l + O)
__device__ float g_po[BB * 16 * 8 * 128 * HH];
__device__ float g_pl[BB * 16 * 8 * 128];

// ---------------------------------------------------------------------------
// helpers
// ---------------------------------------------------------------------------
__device__ __forceinline__ uint32_t bf2(float lo, float hi) {
    uint32_t r;
    asm("cvt.rn.bf16x2.f32 %0, %1, %2;" : "=r"(r) : "f"(hi), "f"(lo));
    return r;
}
__device__ __forceinline__ void split2(float a, float b, uint32_t& h, uint32_t& l) {
    h = bf2(a, b);
    float ah = __uint_as_float(h << 16);
    float bh = __uint_as_float(h & 0xffff0000u);
    l = bf2(a - ah, b - bh);
}
__device__ __forceinline__ float ex2(float x) {
    float r;
    asm("ex2.approx.f32 %0, %1;" : "=f"(r) : "f"(x));
    return r;
}
__device__ __forceinline__ void mma16816(float c[4], const uint32_t a[4],
                                         uint32_t b0, uint32_t b1) {
    asm volatile(
        "mma.sync.aligned.m16n8k16.row.col.f32.bf16.bf16.f32 "
        "{%0,%1,%2,%3}, {%4,%5,%6,%7}, {%8,%9}, {%0,%1,%2,%3};"
        : "+f"(c[0]), "+f"(c[1]), "+f"(c[2]), "+f"(c[3])
        : "r"(a[0]), "r"(a[1]), "r"(a[2]), "r"(a[3]), "r"(b0), "r"(b1));
}
__device__ __forceinline__ void ldsm4(uint32_t* r, uint32_t addr) {
    asm volatile("ldmatrix.sync.aligned.m8n8.x4.shared.b16 {%0,%1,%2,%3}, [%4];"
                 : "=r"(r[0]), "=r"(r[1]), "=r"(r[2]), "=r"(r[3]) : "r"(addr));
}
__device__ __forceinline__ void ldsm4t(uint32_t* r, uint32_t addr) {
    asm volatile("ldmatrix.sync.aligned.m8n8.x4.trans.shared.b16 {%0,%1,%2,%3}, [%4];"
                 : "=r"(r[0]), "=r"(r[1]), "=r"(r[2]), "=r"(r[3]) : "r"(addr));
}
__device__ __forceinline__ void cpa16(uint32_t s, const void* g) {
    asm volatile("cp.async.cg.shared.global [%0], [%1], 16;" :: "r"(s), "l"(g));
}
__device__ __forceinline__ void cpa_commit() { asm volatile("cp.async.commit_group;"); }
__device__ __forceinline__ void cpa_wait0()  { asm volatile("cp.async.wait_group 0;"); }
__device__ __forceinline__ void cpa_wait1()  { asm volatile("cp.async.wait_group 1;"); }

// ---------------------------------------------------------------------------
// fp32 -> bf16 hi/lo planes for the three weight matrices only
// ---------------------------------------------------------------------------
#define N4W (CC * HH / 4)

__global__ void convert_kernel(const float* __restrict__ wq,
                               const float* __restrict__ wk,
                               const float* __restrict__ wv)
{
    int i = blockIdx.x * blockDim.x + threadIdx.x;
    if (i >= 3 * N4W) return;
    int w = i / N4W;
    int idx = i - w * N4W;
    const float* src = (w == 0) ? wq : (w == 1) ? wk : wv;
    uint32_t* dh = g_wh + w * (CC * HH / 2);
    uint32_t* dl = g_wl + w * (CC * HH / 2);
    float4 v = ((const float4*)src)[idx];
    uint32_t h0, l0, h1, l1;
    split2(v.x, v.y, h0, l0);
    split2(v.z, v.w, h1, l1);
    ((uint2*)dh)[idx] = make_uint2(h0, h1);
    ((uint2*)dl)[idx] = make_uint2(l0, l1);
}

// ---------------------------------------------------------------------------
// FUSED Q/K/V projection GEMM: one block computes all three 64x128 outputs.
// x loaded by direct LDG with register prefetch, converted to bf16 hi/lo
// ONCE, A-fragments reused for 3 weight sets.  W cp.async double-buffered.
// Block 64(M) x 128(N) x 3 outputs, BK=32.
// 8 warps = 2(M) x 4(N); warp tile 32x32 (B fragments reused across 2 M-tiles
// -> 32 LDSM vs 52 per warp-iter at identical mma count).
// Grid = 128 blocks (single wave).
// ---------------------------------------------------------------------------
#define XPL 5120                 // one x plane (64 rows x 80B)
#define XHOF(b) ((uint32_t)(b) * XPL)
#define XLOF(b) (2 * XPL + (uint32_t)(b) * XPL)
#define WB0  20480
#define WSEG 8704                // one W plane (32 rows x 272B)
#define WBUF 52224               // 3y x 2 planes
#define WOF(b, y, hl) (WB0 + (uint32_t)(b) * WBUF + (uint32_t)(y) * 17408 + (uint32_t)(hl) * WSEG)
#define PROJ_SMEM 124928

__global__ __launch_bounds__(256) void proj_kernel(const float* __restrict__ x)
{
    extern __shared__ char ps[];
    const uint32_t sb = (uint32_t)__cvta_generic_to_shared(ps);
    const int tid = threadIdx.x, lane = tid & 31, wid = tid >> 5;
    const int wm = wid & 1, wn = wid >> 1;     // 2 M-warps x 4 N-warps
    const int g = lane >> 2, tg = lane & 3;
    const int m0 = blockIdx.x * 64;

    // acc[y][mt*4 + np*2 + h2][4] : warp tile 32(M) x 32(N)
    float acc[3][8][4];
#pragma unroll
    for (int y = 0; y < 3; y++)
#pragma unroll
        for (int nt = 0; nt < 8; nt++)
#pragma unroll
            for (int i = 0; i < 4; i++) acc[y][nt][i] = 0.f;

    const uint32_t a_coff = (lane >> 4) * 16;
    const uint32_t b_coff = (uint32_t)(wn * 64 + (lane >> 4) * 16);  // bytes

    // W loader: 3y x 2 planes x 512 segs = 3072 segs -> 12 per thread
    auto load_W = [&](int k0, int b) {
#pragma unroll
        for (int i = 0; i < 12; i++) {
            int j = tid + i * 256;
            int pl = j >> 9;              // 0..5
            int y = pl >> 1, hl = pl & 1;
            int r = (j >> 4) & 31, cs = j & 15;
            const uint32_t* wsrc = (hl ? g_wl : g_wh) + (size_t)y * (CC * HH / 2)
                                 + (size_t)(k0 + r) * 64 + cs * 4;
            cpa16(sb + WOF(b, y, hl) + r * 272 + cs * 16, wsrc);
        }
    };

    // x register prefetch: each thread 1 row x 8 cols
    const int xrow = tid >> 2;
    const float* xp = x + (size_t)(m0 + xrow) * CC + (tid & 3) * 8;
    float4 xr0, xr1;

    load_W(0, 0);
    cpa_commit();
    xr0 = *(const float4*)(xp);
    xr1 = *(const float4*)(xp + 4);

    for (int it = 0; it < 32; it++) {
        const int b = it & 1;
        if (it + 1 < 32) {
            load_W((it + 1) * 32, b ^ 1);
            cpa_commit();
            cpa_wait1();
        } else {
            cpa_wait0();
        }

        // convert prefetched x regs -> hi/lo planes [b]
        {
            uint32_t hh[4], ll[4];
            split2(xr0.x, xr0.y, hh[0], ll[0]);
            split2(xr0.z, xr0.w, hh[1], ll[1]);
            split2(xr1.x, xr1.y, hh[2], ll[2]);
            split2(xr1.z, xr1.w, hh[3], ll[3]);
            *(uint4*)(ps + XHOF(b) + xrow * 80 + (tid & 3) * 16) =
                make_uint4(hh[0], hh[1], hh[2], hh[3]);
            *(uint4*)(ps + XLOF(b) + xrow * 80 + (tid & 3) * 16) =
                make_uint4(ll[0], ll[1], ll[2], ll[3]);
        }
        __syncthreads();

        // prefetch x for next iter
        if (it + 1 < 32) {
            xr0 = *(const float4*)(xp + (it + 1) * 32);
            xr1 = *(const float4*)(xp + (it + 1) * 32 + 4);
        }

#pragma unroll
        for (int ks = 0; ks < 2; ks++) {
            uint32_t ah[2][4], al[2][4];
#pragma unroll
            for (int mt = 0; mt < 2; mt++) {
                uint32_t r = wm * 32 + mt * 16 + (lane & 15);
                ldsm4(ah[mt], sb + XHOF(b) + r * 80 + ks * 32 + a_coff);
                ldsm4(al[mt], sb + XLOF(b) + r * 80 + ks * 32 + a_coff);
            }
#pragma unroll
            for (int y = 0; y < 3; y++) {
#pragma unroll
                for (int np = 0; np < 2; np++) {
                    uint32_t bh[4], bl[4];
                    uint32_t r = ks * 16 + (lane & 15);
                    ldsm4t(bh, sb + WOF(b, y, 0) + r * 272 + b_coff + np * 32);
                    ldsm4t(bl, sb + WOF(b, y, 1) + r * 272 + b_coff + np * 32);
#pragma unroll
                    for (int mt = 0; mt < 2; mt++)
#pragma unroll
                        for (int h2 = 0; h2 < 2; h2++) {
                            float* c = acc[y][mt * 4 + np * 2 + h2];
                            mma16816(c, ah[mt], bh[2 * h2], bh[2 * h2 + 1]);
                            mma16816(c, ah[mt], bl[2 * h2], bl[2 * h2 + 1]);
                            mma16816(c, al[mt], bh[2 * h2], bh[2 * h2 + 1]);
                        }
                }
            }
        }
        __syncthreads();
    }

    // epilogue: q pre-scaled by C^-0.5 * log2(e)
#pragma unroll
    for (int y = 0; y < 3; y++) {
        uint32_t* oh = (y == 0) ? g_qh : (y == 1) ? g_kh : g_vh;
        uint32_t* ol = (y == 0) ? g_ql : (y == 1) ? g_kl : g_vl;
        const float sc = (y == 0) ? 0.03125f * 1.44269504f : 1.0f;
#pragma unroll
        for (int mt = 0; mt < 2; mt++) {
            const int r1 = m0 + wm * 32 + mt * 16 + g;
#pragma unroll
            for (int np = 0; np < 2; np++)
#pragma unroll
                for (int h2 = 0; h2 < 2; h2++) {
                    const float* a = acc[y][mt * 4 + np * 2 + h2];
                    const int c = wn * 32 + np * 16 + h2 * 8 + 2 * tg;
                    uint32_t h, l;
                    split2(a[0] * sc, a[1] * sc, h, l);
                    oh[(size_t)r1 * 64 + (c >> 1)] = h;
                    ol[(size_t)r1 * 64 + (c >> 1)] = l;
                    split2(a[2] * sc, a[3] * sc, h, l);
                    oh[(size_t)(r1 + 8) * 64 + (c >> 1)] = h;
                    ol[(size_t)(r1 + 8) * 64 + (c >> 1)] = l;
                }
        }
    }
}

// ---------------------------------------------------------------------------
// Flash attention, bf16 mma 3-term split, cp.async double-buffered K/V,
// FIXED-MAX softmax (M=16).  Block = 128 q rows x chunk of <=4 key tiles.
// (unchanged from best)
// ---------------------------------------------------------------------------
#define SP 272
#define AKH 0
#define AKL 17408
#define AVH 34816
#define AVL 52224
#define ATT_BUF 69632
#define ATT_SMEM (2 * ATT_BUF)
#define SMAX 16.0f

__global__ __launch_bounds__(256) void attn_kernel(float* __restrict__ out)
{
    const int qb = blockIdx.x;                 // 0..15
    const int b  = blockIdx.y;                 // 0..3
    const int ch = blockIdx.z;                 // 0..7
    const int ntiles = 2 * qb + 2;
    if (ch * 4 >= ntiles) return;

    extern __shared__ char as_[];
    const uint32_t sb = (uint32_t)__cvta_generic_to_shared(as_);
    const int tid = threadIdx.x, lane = tid & 31, w = tid >> 5;
    const int g = lane >> 2, tg = lane & 3;
    const int r0 = qb * 128;

    // ---- stage Q (hi at 0, lo at AVH), async, then to registers
    {
        const uint32_t* sh = g_qh + (size_t)b * TT * 64;
        const uint32_t* sl = g_ql + (size_t)b * TT * 64;
#pragma unroll
        for (int i = 0; i < 8; i++) {
            int s = tid + i * 256;
            int row = s >> 4, cs = s & 15;
            size_t gi = (size_t)(r0 + row) * 64 + cs * 4;
            cpa16(sb + row * SP + cs * 16, sh + gi);
            cpa16(sb + AVH + row * SP + cs * 16, sl + gi);
        }
        cpa_commit();
        cpa_wait0();
    }
    __syncthreads();
    uint32_t qh[8][4], ql[8][4];
    {
        const uint32_t br = w * 16 + (lane & 15);
        const uint32_t co = (lane >> 4) * 16;
#pragma unroll
        for (int ks = 0; ks < 8; ks++) {
            ldsm4(qh[ks], sb + br * SP + ks * 32 + co);
            ldsm4(ql[ks], sb + AVH + br * SP + ks * 32 + co);
        }
    }
    __syncthreads();

    float o[16][4];
#pragma unroll
    for (int nt = 0; nt < 16; nt++)
#pragma unroll
        for (int i = 0; i < 4; i++) o[nt][i] = 0.f;
    float l0 = 0.f, l1 = 0.f;

    const uint32_t* khp = g_kh + (size_t)b * TT * 64;
    const uint32_t* klp = g_kl + (size_t)b * TT * 64;
    const uint32_t* vhp = g_vh + (size_t)b * TT * 64;
    const uint32_t* vlp = g_vl + (size_t)b * TT * 64;

    auto load_tile = [&](int j0, uint32_t bo) {
#pragma unroll
        for (int i = 0; i < 4; i++) {
            int s = tid + i * 256;
            int row = s >> 4, cs = s & 15;
            size_t gi = (size_t)(j0 + row) * 64 + cs * 4;
            uint32_t so = bo + row * SP + cs * 16;
            cpa16(sb + so + AKH, khp + gi);
            cpa16(sb + so + AKL, klp + gi);
            cpa16(sb + so + AVH, vhp + gi);
            cpa16(sb + so + AVL, vlp + gi);
        }
    };

    const int jt0 = ch * 4;
    const int n = min(jt0 + 4, ntiles) - jt0;

    load_tile(jt0 * 64, 0);
    cpa_commit();

    for (int it = 0; it < n; it++) {
        const int jt = jt0 + it;
        const int j0 = jt * 64;
        const uint32_t bo = (uint32_t)(it & 1) * ATT_BUF;
        if (it + 1 < n) {
            load_tile((jt + 1) * 64, bo ^ ATT_BUF);
            cpa_commit();
            cpa_wait1();
        } else {
            cpa_wait0();
        }
        __syncthreads();

        // ---- S = Q K^T  (q pre-scaled by 1/32*log2e)
        float s_[8][4];
#pragma unroll
        for (int nt = 0; nt < 8; nt++)
#pragma unroll
            for (int i = 0; i < 4; i++) s_[nt][i] = 0.f;
        {
            const uint32_t kr = (lane & 7);
            const uint32_t kc = (lane >> 3) * 16;
#pragma unroll
            for (int kp = 0; kp < 4; kp++) {
#pragma unroll
                for (int nt = 0; nt < 8; nt++) {
                    uint32_t kh4[4], kl4[4];
                    uint32_t ro = bo + (nt * 8 + kr) * SP + kp * 64 + kc;
                    ldsm4(kh4, sb + AKH + ro);
                    ldsm4(kl4, sb + AKL + ro);
                    mma16816(s_[nt], qh[2 * kp],     kh4[0], kh4[1]);
                    mma16816(s_[nt], qh[2 * kp],     kl4[0], kl4[1]);
                    mma16816(s_[nt], ql[2 * kp],     kh4[0], kh4[1]);
                    mma16816(s_[nt], qh[2 * kp + 1], kh4[2], kh4[3]);
                    mma16816(s_[nt], qh[2 * kp + 1], kl4[2], kl4[3]);
                    mma16816(s_[nt], ql[2 * kp + 1], kh4[2], kh4[3]);
                }
            }
        }

        // ---- causal mask
        if (jt >= 2 * qb) {
            const int rA = r0 + w * 16 + g, rB = rA + 8;
#pragma unroll
            for (int nt = 0; nt < 8; nt++) {
                const int c0 = j0 + nt * 8 + 2 * tg, c1 = c0 + 1;
                if (c0 > rA) s_[nt][0] = -CUDART_INF_F;
                if (c1 > rA) s_[nt][1] = -CUDART_INF_F;
                if (c0 > rB) s_[nt][2] = -CUDART_INF_F;
                if (c1 > rB) s_[nt][3] = -CUDART_INF_F;
            }
        }

        // ---- fixed-max softmax: p = 2^(s - 16)
#pragma unroll
        for (int nt = 0; nt < 8; nt++) {
            s_[nt][0] = ex2(s_[nt][0] - SMAX);
            s_[nt][1] = ex2(s_[nt][1] - SMAX);
            s_[nt][2] = ex2(s_[nt][2] - SMAX);
            s_[nt][3] = ex2(s_[nt][3] - SMAX);
            l0 += s_[nt][0] + s_[nt][1];
            l1 += s_[nt][2] + s_[nt][3];
        }

        // ---- O += P V (P split to bf16 in registers)
#pragma unroll
        for (int ks = 0; ks < 4; ks++) {
            uint32_t pah[4], pal[4];
            split2(s_[2 * ks][0],     s_[2 * ks][1],     pah[0], pal[0]);
            split2(s_[2 * ks][2],     s_[2 * ks][3],     pah[1], pal[1]);
            split2(s_[2 * ks + 1][0], s_[2 * ks + 1][1], pah[2], pal[2]);
            split2(s_[2 * ks + 1][2], s_[2 * ks + 1][3], pah[3], pal[3]);
            const uint32_t vr = bo + (ks * 16 + (lane & 15)) * SP + (lane >> 4) * 16;
#pragma unroll
            for (int np = 0; np < 8; np++) {
                uint32_t vh4[4], vl4[4];
                ldsm4t(vh4, sb + AVH + vr + np * 32);
                ldsm4t(vl4, sb + AVL + vr + np * 32);
                float* c0 = o[2 * np];
                float* c1 = o[2 * np + 1];
                mma16816(c0, pah, vh4[0], vh4[1]);
                mma16816(c0, pah, vl4[0], vl4[1]);
                mma16816(c0, pal, vh4[0], vh4[1]);
                mma16816(c1, pah, vh4[2], vh4[3]);
                mma16816(c1, pah, vl4[2], vl4[3]);
                mma16816(c1, pal, vh4[2], vh4[3]);
            }
        }
        __syncthreads();
    }

    // reduce row sums across the quad (once per block)
    l0 += __shfl_xor_sync(0xffffffffu, l0, 1);
    l0 += __shfl_xor_sync(0xffffffffu, l0, 2);
    l1 += __shfl_xor_sync(0xffffffffu, l1, 1);
    l1 += __shfl_xor_sync(0xffffffffu, l1, 2);

    const int rA = w * 16 + g;
    if (ntiles <= 4) {
        const float inv0 = 1.f / l0, inv1 = 1.f / l1;
        float* op = out + ((size_t)b * TT + r0) * HH;
#pragma unroll
        for (int nt = 0; nt < 16; nt++) {
            const int c = nt * 8 + 2 * tg;
            *(float2*)(op + (size_t)rA * HH + c) =
                make_float2(o[nt][0] * inv0, o[nt][1] * inv0);
            *(float2*)(op + (size_t)(rA + 8) * HH + c) =
                make_float2(o[nt][2] * inv1, o[nt][3] * inv1);
        }
    } else {
        const size_t pb = (size_t)((b * 16 + qb) * 8 + ch);
        float* po = g_po + pb * 128 * 128;
#pragma unroll
        for (int nt = 0; nt < 16; nt++) {
            const int c = nt * 8 + 2 * tg;
            *(float2*)(po + (size_t)rA * 128 + c)       = make_float2(o[nt][0], o[nt][1]);
            *(float2*)(po + (size_t)(rA + 8) * 128 + c) = make_float2(o[nt][2], o[nt][3]);
        }
        if (tg == 0) {
            g_pl[pb * 128 + rA] = l0;  g_pl[pb * 128 + rA + 8] = l1;
        }
    }
}

// ---------------------------------------------------------------------------
// Combine split-KV partials (qb >= 2): plain sums (fixed-max -> weights = 1).
// One thread per 8 output floats.
// ---------------------------------------------------------------------------
__global__ __launch_bounds__(256) void combine_kernel(float* __restrict__ out)
{
    const int qb  = 2 + (blockIdx.x >> 3);
    const int sub = blockIdx.x & 7;
    const int b   = blockIdx.y;
    const int nc  = (2 * qb + 5) >> 2;

    const int e   = sub * 256 + threadIdx.x;
    const int row = e >> 4;
    const int c8  = (e & 15) * 8;

    const size_t pb = (size_t)(b * 16 + qb) * 8;

    float l = 0.f;
#pragma unroll 4
    for (int c = 0; c < nc; c++)
        l += __ldg(&g_pl[(pb + c) * 128 + row]);
    const float inv = 1.f / l;

    float a0 = 0.f, a1 = 0.f, a2 = 0.f, a3 = 0.f;
    float b0 = 0.f, b1 = 0.f, b2 = 0.f, b3 = 0.f;
#pragma unroll 4
    for (int c = 0; c < nc; c++) {
        const float4* base = (const float4*)(g_po + ((pb + c) * 128 + row) * 128 + c8);
        const float4 p = __ldg(base);
        const float4 q = __ldg(base + 1);
        a0 += p.x; a1 += p.y; a2 += p.z; a3 += p.w;
        b0 += q.x; b1 += q.y; b2 += q.z; b3 += q.w;
    }
    float* op = out + ((size_t)b * TT + qb * 128 + row) * HH + c8;
    *(float4*)(op)     = make_float4(a0 * inv, a1 * inv, a2 * inv, a3 * inv);
    *(float4*)(op + 4) = make_float4(b0 * inv, b1 * inv, b2 * inv, b3 * inv);
}

// ---------------------------------------------------------------------------
extern "C" void kernel_launch(void* const* d_in, const int* in_sizes, int n_in,
                              void* d_out, int out_size)
{
    (void)in_sizes; (void)n_in; (void)out_size;
    const float* x  = (const float*)d_in[0];
    const float* Wq = (const float*)d_in[1];
    const float* Wk = (const float*)d_in[2];
    const float* Wv = (const float*)d_in[3];
    float* out = (float*)d_out;

    convert_kernel<<<(3 * N4W + 255) / 256, 256>>>(Wq, Wk, Wv);

    cudaFuncSetAttribute(proj_kernel,
                         cudaFuncAttributeMaxDynamicSharedMemorySize, PROJ_SMEM);
    proj_kernel<<<BT / 64, 256, PROJ_SMEM>>>(x);

    cudaFuncSetAttribute(attn_kernel,
                         cudaFuncAttributeMaxDynamicSharedMemorySize, ATT_SMEM);
    dim3 agrid(16, BB, 8);
    attn_kernel<<<agrid, 256, ATT_SMEM>>>(out);

    dim3 cgrid(14 * 8, BB);
    combine_kernel<<<cgrid, 256>>>(out);
}